// round 16
// baseline (speedup 1.0000x reference)
#include <cuda_runtime.h>
#include <cuda_bf16.h>
#include <cstdint>
#include <math.h>

// Problem constants
#define BATCH   8192
#define DIM     1024
#define SKETCH  8192
#define OUT     512
#define LN_EPS  1e-5f

#define MCAP    1024      // |J| <= 1024 (hard bound)
#define TB      64        // batch rows per CTA
#define NTHR    1024      // 32 warps
#define KCH     128       // K per chunk (64 kpairs)
#define APKS    72        // A tile row stride (uint2 units)
#define WBS     72        // WB staging stride (uint2 units)

// -------- dynamic smem layout (bytes) --------------------------------------
#define OFF_A    0                       // A [64 kp][72] uint2 {hi,lo} = 36864
#define OFF_WB   36864                   // WB [128 n][72] uint2        = 73728
#define OFF_BIAS 110592                  // 512 f
#define OFF_PS   112640                  // [64][8] f
#define OFF_PQ   114688                  // [64][8] f
#define OFF_MU   116736                  // 64 f
#define OFF_RS   116992                  // 64 f
#define DSM_BYTES 117760

// ---------------- device globals (scratch; no cudaMalloc allowed) ----------
__device__ unsigned int g_idx1[DIM];
__device__ unsigned int g_idx2[DIM];
__device__ int          g_m;
__device__ int          g_fallback;
__device__ int          g_colJ[MCAP];
__device__ int          g_cp1[MCAP + 1];
__device__ int          g_cp2[MCAP + 1];
__device__ unsigned int g_ent1[MCAP];
__device__ unsigned int g_ent2[MCAP];
__device__ ulonglong2   g_rec[MCAP];
// pre-split packed W, hi/lo interleaved: [n=512][kpair=512] uint2 (2MB)
__device__ uint2        g_WB[512 * 512];

// -------- helpers ----------------------------------------------------------
__device__ __forceinline__ float sgnapply(float x, unsigned e) {
    return __int_as_float(__float_as_int(x) ^ (int)((e & 1024u) << 21));
}
// bf16 3-split store into interleaved A tile: uint2{hi_pair, lo_pair}
__device__ __forceinline__ void put_split(char* b, int cl, int r, float v) {
    __nv_bfloat16 h = __float2bfloat16(v);
    __nv_bfloat16 l = __float2bfloat16(v - __bfloat162float(h));
    unsigned off = (unsigned)(((cl >> 1) * APKS + r) * 8 + (cl & 1) * 2);
    *(__nv_bfloat16*)(b + off)     = h;
    *(__nv_bfloat16*)(b + off + 4) = l;
}
// m16n8k16 bf16 MMA, fp32 accumulate in place
__device__ __forceinline__ void mma_bf16(float* d, const unsigned* a, const unsigned* b) {
    asm volatile(
        "mma.sync.aligned.m16n8k16.row.col.f32.bf16.bf16.f32 "
        "{%0,%1,%2,%3}, {%4,%5,%6,%7}, {%8,%9}, {%0,%1,%2,%3};"
        : "+f"(d[0]), "+f"(d[1]), "+f"(d[2]), "+f"(d[3])
        : "r"(a[0]), "r"(a[1]), "r"(a[2]), "r"(a[3]), "r"(b[0]), "r"(b[1]));
}

// -------- warp-shuffle block scan (1024 threads) ---------------------------
__device__ __forceinline__ int block_scan_incl(int val, int t, int* ws) {
    const unsigned full = 0xFFFFFFFFu;
    int lane = t & 31;
#pragma unroll
    for (int o = 1; o < 32; o <<= 1) {
        int n = __shfl_up_sync(full, val, o);
        if (lane >= o) val += n;
    }
    if (lane == 31) ws[t >> 5] = val;
    __syncthreads();
    if (t < 32) {
        int v = ws[t];
#pragma unroll
        for (int o = 1; o < 32; o <<= 1) {
            int n = __shfl_up_sync(full, v, o);
            if (t >= o) v += n;
        }
        ws[t] = v;
    }
    __syncthreads();
    if (t >= 32) val += ws[(t >> 5) - 1];
    return val;
}

// ---------------------------------------------------------------------------
// Kernel A: find the single nonzero per row of S1/S2.
// ---------------------------------------------------------------------------
__global__ void k_extract(const float* __restrict__ S1,
                          const float* __restrict__ S2)
{
    int row = blockIdx.x;
    const float* S;
    unsigned int* outp;
    if (row < DIM) { S = S1; outp = g_idx1; }
    else           { S = S2; outp = g_idx2; row -= DIM; }

    const float4* p = (const float4*)(S + (size_t)row * SKETCH);
    int t = threadIdx.x;
#pragma unroll
    for (int k = 0; k < SKETCH / 4 / 256; k++) {
        int v4 = t + k * 256;
        float4 v = p[v4];
        int base = v4 * 4;
        if (v.x != 0.0f) outp[row] = (unsigned)(base + 0) | (v.x < 0.0f ? 0x80000000u : 0u);
        if (v.y != 0.0f) outp[row] = (unsigned)(base + 1) | (v.y < 0.0f ? 0x80000000u : 0u);
        if (v.z != 0.0f) outp[row] = (unsigned)(base + 2) | (v.z < 0.0f ? 0x80000000u : 0u);
        if (v.w != 0.0f) outp[row] = (unsigned)(base + 3) | (v.w < 0.0f ? 0x80000000u : 0u);
    }
}

// ---------------------------------------------------------------------------
// Kernel B: build compact structure + CSR + packed records. 1 CTA, 1024 thr.
// ---------------------------------------------------------------------------
__global__ void k_build()
{
    __shared__ int cnt[SKETCH];
    __shared__ int colcnt[MCAP];
    __shared__ int ws[32];
    __shared__ int sh_total;

    int t = threadIdx.x;
    for (int j = t; j < SKETCH; j += 1024) cnt[j] = 0;
    if (t == 0) g_fallback = 0;
    __syncthreads();

    unsigned u1 = g_idx1[t];
    unsigned u2 = g_idx2[t];
    atomicAdd(&cnt[u1 & (SKETCH - 1)], 1);
    atomicAdd(&cnt[u2 & (SKETCH - 1)], 1 << 16);
    __syncthreads();

    int q = 0;
    int qual[8];
#pragma unroll
    for (int u = 0; u < 8; u++) {
        int j = t * 8 + u;
        int c = cnt[j];
        qual[u] = ((c & 0xFFFF) > 0 && (c >> 16) > 0) ? 1 : 0;
        q += qual[u];
    }
    int incl = block_scan_incl(q, t, ws);
    int excl = incl - q;
    if (t == 1023) sh_total = incl;
    __syncthreads();
    int total = sh_total;

#pragma unroll
    for (int u = 0; u < 8; u++) {
        int j = t * 8 + u;
        if (qual[u]) { g_colJ[excl] = j; cnt[j] = excl; excl++; }
        else         { cnt[j] = -1; }
    }
    if (t == 0) g_m = total;
    __syncthreads();

    int c1 = cnt[u1 & (SKETCH - 1)];
    int c2 = cnt[u2 & (SKETCH - 1)];
#pragma unroll
    for (int s = 0; s < 2; s++) {
        int cc = s ? c2 : c1;
        unsigned uu = s ? u2 : u1;
        int* cp = s ? g_cp2 : g_cp1;
        unsigned int* ent = s ? g_ent2 : g_ent1;

        colcnt[t] = 0;
        __syncthreads();
        if (cc >= 0) atomicAdd(&colcnt[cc], 1);
        __syncthreads();

        int myc = colcnt[t];
        int inc2 = block_scan_incl(myc, t, ws);
        int ex = inc2 - myc;
        cp[t] = ex;
        if (t == 1023) cp[1024] = inc2;
        __syncthreads();
        colcnt[t] = ex;
        __syncthreads();
        if (cc >= 0) {
            int slot = atomicAdd(&colcnt[cc], 1);
            ent[slot] = (((uu >> 31) & 1u) << 15) | (unsigned)t;
        }
        __syncthreads();
    }

    if (t < total) {
        unsigned long long w[2];
#pragma unroll
        for (int s = 0; s < 2; s++) {
            const int* cp = s ? g_cp2 : g_cp1;
            const unsigned int* ent = s ? g_ent2 : g_ent1;
            int e0 = cp[t], e1 = cp[t + 1];
            int cnte = e1 - e0;
            if (cnte > 4) { atomicOr(&g_fallback, 1); cnte = 4; }
            unsigned long long u = 0;
            for (int k = 0; k < cnte; k++) {
                unsigned v = ent[e0 + k];
                u |= (unsigned long long)((v & 1023u) | (((v >> 15) & 1u) << 10)) << (11 * k);
            }
            u |= (unsigned long long)cnte << 60;
            w[s] = u;
        }
        ulonglong2 r;
        r.x = w[0];
        r.y = w[1];
        g_rec[t] = r;
    }
}

// ---------------------------------------------------------------------------
// Kernel Bw: pre-split W into packed bf16x2 hi/lo, interleaved uint2,
// layout [n][kpair]. Word (n,kp) = {hi pair, lo pair} for cols 2kp, 2kp+1.
// ---------------------------------------------------------------------------
__global__ void k_wprep(const float* __restrict__ W)
{
    int m = g_m;
    int idx = blockIdx.x * 256 + threadIdx.x;   // 512 n x 512 kp
    int kp = idx & 511;
    int n  = idx >> 9;
    int c0 = 2 * kp, c1 = 2 * kp + 1;
    float v0 = (c0 < m) ? __ldg(&W[(size_t)g_colJ[c0] * OUT + n]) : 0.0f;
    float v1 = (c1 < m) ? __ldg(&W[(size_t)g_colJ[c1] * OUT + n]) : 0.0f;
    __nv_bfloat16 h0 = __float2bfloat16(v0);
    __nv_bfloat16 l0 = __float2bfloat16(v0 - __bfloat162float(h0));
    __nv_bfloat16 h1 = __float2bfloat16(v1);
    __nv_bfloat16 l1 = __float2bfloat16(v1 - __bfloat162float(h1));
    unsigned wh = (unsigned)__bfloat16_as_ushort(h0) |
                  ((unsigned)__bfloat16_as_ushort(h1) << 16);
    unsigned wl = (unsigned)__bfloat16_as_ushort(l0) |
                  ((unsigned)__bfloat16_as_ushort(l1) << 16);
    g_WB[n * 512 + kp] = make_uint2(wh, wl);
}

// ---------------------------------------------------------------------------
// Main fused kernel. TB=64 rows/CTA, 1024 threads (32 warps), 128 CTAs.
//  Phase 1 (one barrier): WB(nt=0) staging + A pad-zero + gather, all
//  disjoint smem, staging LDGs hide under gather latency.
//  GEMM: mma.sync bf16 m16n8k16 3-split; interleaved hi/lo -> every
//  fragment load is one LDS.64 (half the instruction count of round 15).
//  Epilogue: +bias, LayerNorm (shfl + smem partials), ReLU.
// ---------------------------------------------------------------------------
__global__ void __launch_bounds__(NTHR, 1)
k_main(const float* __restrict__ x1, const float* __restrict__ x2,
       const float* __restrict__ bias, const float* __restrict__ gamma,
       const float* __restrict__ beta, float* __restrict__ out)
{
    extern __shared__ __align__(16) char dsm[];
    const uint2* AW = (const uint2*)(dsm + OFF_A);
    uint2* WB = (uint2*)(dsm + OFF_WB);

    int tid  = threadIdx.x;
    int lane = tid & 31;
    int wrp  = tid >> 5;
    int g    = lane >> 2;         // 0..7
    int t4   = lane & 3;          // 0..3
    int mt   = wrp >> 3;          // 0..3  -> rows [mt*16, +16)
    int ng   = wrp & 7;           // 0..7  -> cols [ng*16, +16) within n-tile
    int b0   = blockIdx.x * TB;

    int m  = g_m;
    int fb = g_fallback;
    int nch = (m + KCH - 1) / KCH;

    // accumulators
    float acc[4][2][4];
#pragma unroll
    for (int a = 0; a < 4; a++)
#pragma unroll
        for (int b = 0; b < 2; b++)
#pragma unroll
            for (int c = 0; c < 4; c++) acc[a][b][c] = 0.0f;

    for (int i = tid; i < OUT; i += NTHR)
        *(float*)(dsm + OFF_BIAS + i * 4) = __ldg(&bias[i]);

    for (int ch = 0; ch < nch; ch++) {
        int ck0 = ch * KCH;
        int Cn  = min(KCH, m - ck0);
        int ClPad = (Cn + 1) & ~1;         // even column bound written by gather
        int kp0 = ClPad >> 1;              // first kp needing explicit zero

        // ---- phase 1: WB(nt=0) staging + A pad-zero + gather ----
        {   // stage WB slice for nt=0 (uint4: 2 kp per load)
            for (int i = tid; i < 4096; i += NTHR) {
                int n   = i >> 5;
                int kp2 = (i & 31) * 2;
                uint4 v = __ldg((const uint4*)&g_WB[(size_t)n * 512 + ck0 / 2 + kp2]);
                *(uint4*)&WB[n * WBS + kp2] = v;
            }
            // zero the pad region kp in [kp0, 64)
            int nz = (64 - kp0) * APKS;
            for (int i = tid; i < nz; i += NTHR)
                ((uint2*)(dsm + OFF_A))[kp0 * APKS + i] = make_uint2(0, 0);
        }
        if (!fb) {
            int nw = ClPad * 32;
            for (int p = tid; p < nw; p += NTHR) {
                int cl = p >> 5;
                int r  = p & 31;
                int c  = ck0 + cl;
                if (c >= m) {
                    put_split(dsm + OFF_A, cl, r, 0.0f);
                    put_split(dsm + OFF_A, cl, r + 32, 0.0f);
                    continue;
                }
                ulonglong2 rec = __ldg(&g_rec[c]);
                size_t ro0 = (size_t)(b0 + r) * DIM;
                size_t ro1 = (size_t)(b0 + r + 32) * DIM;

                unsigned long long u = rec.x;
                int cnt1 = (int)(u >> 60);
                unsigned e = (unsigned)u & 0x7FFu;
                float s1a = sgnapply(__ldg(&x1[ro0 + (e & 1023u)]), e);
                float s1b = sgnapply(__ldg(&x1[ro1 + (e & 1023u)]), e);
#pragma unroll
                for (int k = 1; k < 4; k++) {
                    if (k < cnt1) {
                        e = (unsigned)(u >> (11 * k)) & 0x7FFu;
                        s1a += sgnapply(__ldg(&x1[ro0 + (e & 1023u)]), e);
                        s1b += sgnapply(__ldg(&x1[ro1 + (e & 1023u)]), e);
                    }
                }
                u = rec.y;
                int cnt2 = (int)(u >> 60);
                e = (unsigned)u & 0x7FFu;
                float s2a = sgnapply(__ldg(&x2[ro0 + (e & 1023u)]), e);
                float s2b = sgnapply(__ldg(&x2[ro1 + (e & 1023u)]), e);
#pragma unroll
                for (int k = 1; k < 4; k++) {
                    if (k < cnt2) {
                        e = (unsigned)(u >> (11 * k)) & 0x7FFu;
                        s2a += sgnapply(__ldg(&x2[ro0 + (e & 1023u)]), e);
                        s2b += sgnapply(__ldg(&x2[ro1 + (e & 1023u)]), e);
                    }
                }
                put_split(dsm + OFF_A, cl, r,      s1a * s2a);
                put_split(dsm + OFF_A, cl, r + 32, s1b * s2b);
            }
        } else {
            int nw = ClPad * TB;
            for (int p = tid; p < nw; p += NTHR) {
                int cl = p >> 6;
                int r  = p & 63;
                int c  = ck0 + cl;
                float v = 0.0f;
                if (c < m) {
                    size_t rowoff = (size_t)(b0 + r) * DIM;
                    float s1 = 0.0f;
                    int e0 = __ldg(&g_cp1[c]), e1 = __ldg(&g_cp1[c + 1]);
                    for (int e = e0; e < e1; e++) {
                        unsigned u = __ldg(&g_ent1[e]);
                        float x = __ldg(&x1[rowoff + (u & 1023u)]);
                        s1 += (u & 0x8000u) ? -x : x;
                    }
                    float s2 = 0.0f;
                    int f0 = __ldg(&g_cp2[c]), f1 = __ldg(&g_cp2[c + 1]);
                    for (int e = f0; e < f1; e++) {
                        unsigned u = __ldg(&g_ent2[e]);
                        float x = __ldg(&x2[rowoff + (u & 1023u)]);
                        s2 += (u & 0x8000u) ? -x : x;
                    }
                    v = s1 * s2;
                }
                put_split(dsm + OFF_A, cl, r, v);
            }
        }
        __syncthreads();

        // ---- 4 n-tiles of 128 cols ----
#pragma unroll
        for (int nt = 0; nt < 4; nt++) {
            if (nt > 0) {
                for (int i = tid; i < 4096; i += NTHR) {
                    int n   = i >> 5;
                    int kp2 = (i & 31) * 2;
                    uint4 v = __ldg((const uint4*)
                        &g_WB[(size_t)(nt * 128 + n) * 512 + ck0 / 2 + kp2]);
                    *(uint4*)&WB[n * WBS + kp2] = v;
                }
                __syncthreads();
            }

            int arow = mt * 16 + g;
#pragma unroll
            for (int ks = 0; ks < 8; ks++) {
                int kpa = ks * 8 + t4;
                uint2 A0 = AW[kpa * APKS + arow];
                uint2 A1 = AW[kpa * APKS + arow + 8];
                uint2 A2 = AW[(kpa + 4) * APKS + arow];
                uint2 A3 = AW[(kpa + 4) * APKS + arow + 8];
                unsigned ah[4] = {A0.x, A1.x, A2.x, A3.x};
                unsigned al[4] = {A0.y, A1.y, A2.y, A3.y};
#pragma unroll
                for (int n8 = 0; n8 < 2; n8++) {
                    int nrow = ng * 16 + n8 * 8 + g;
                    uint2 B0 = WB[nrow * WBS + kpa];
                    uint2 B1 = WB[nrow * WBS + kpa + 4];
                    unsigned bh[2] = {B0.x, B1.x};
                    unsigned bl[2] = {B0.y, B1.y};
                    mma_bf16(acc[nt][n8], ah, bh);
                    mma_bf16(acc[nt][n8], ah, bl);
                    mma_bf16(acc[nt][n8], al, bh);
                }
            }
            __syncthreads();   // WB restaged next nt / A rewritten next chunk
        }
    }

    // -------- epilogue: +bias, LN stats --------------------------------
    float* PS = (float*)(dsm + OFF_PS);
    float* PQ = (float*)(dsm + OFF_PQ);
    float sA = 0.0f, qA = 0.0f, sB = 0.0f, qB = 0.0f;
#pragma unroll
    for (int nt = 0; nt < 4; nt++)
#pragma unroll
        for (int n8 = 0; n8 < 2; n8++) {
            int col = nt * 128 + ng * 16 + n8 * 8 + 2 * t4;
            float2 bb = *(float2*)(dsm + OFF_BIAS + col * 4);
            float* a4 = acc[nt][n8];
            a4[0] += bb.x; a4[1] += bb.y;
            a4[2] += bb.x; a4[3] += bb.y;
            sA += a4[0] + a4[1]; qA += a4[0] * a4[0] + a4[1] * a4[1];
            sB += a4[2] + a4[3]; qB += a4[2] * a4[2] + a4[3] * a4[3];
        }
#pragma unroll
    for (int o = 1; o < 4; o <<= 1) {
        sA += __shfl_xor_sync(0xFFFFFFFFu, sA, o);
        qA += __shfl_xor_sync(0xFFFFFFFFu, qA, o);
        sB += __shfl_xor_sync(0xFFFFFFFFu, sB, o);
        qB += __shfl_xor_sync(0xFFFFFFFFu, qB, o);
    }
    if (t4 == 0) {
        int rA = mt * 16 + g, rB = rA + 8;
        PS[rA * 8 + ng] = sA; PQ[rA * 8 + ng] = qA;
        PS[rB * 8 + ng] = sB; PQ[rB * 8 + ng] = qB;
    }
    __syncthreads();
    if (tid < TB) {
        float s = 0.0f, q = 0.0f;
#pragma unroll
        for (int w = 0; w < 8; w++) { s += PS[tid * 8 + w]; q += PQ[tid * 8 + w]; }
        float mu  = s * (1.0f / OUT);
        float var = q * (1.0f / OUT) - mu * mu;
        *(float*)(dsm + OFF_MU + tid * 4) = mu;
        *(float*)(dsm + OFF_RS + tid * 4) = rsqrtf(var + LN_EPS);
    }
    __syncthreads();

    // -------- normalize + affine + ReLU + store ------------------------
    {
        int rA = mt * 16 + g, rB = rA + 8;
        float muA = *(float*)(dsm + OFF_MU + rA * 4);
        float rsA = *(float*)(dsm + OFF_RS + rA * 4);
        float muB = *(float*)(dsm + OFF_MU + rB * 4);
        float rsB = *(float*)(dsm + OFF_RS + rB * 4);
        float* outA = out + (size_t)(b0 + rA) * OUT;
        float* outB = out + (size_t)(b0 + rB) * OUT;
#pragma unroll
        for (int nt = 0; nt < 4; nt++)
#pragma unroll
            for (int n8 = 0; n8 < 2; n8++) {
                int col = nt * 128 + ng * 16 + n8 * 8 + 2 * t4;
                float2 gg = __ldg((const float2*)(gamma + col));
                float2 ee = __ldg((const float2*)(beta + col));
                const float* a4 = acc[nt][n8];
                float2 oA, oB;
                oA.x = fmaxf((a4[0] - muA) * rsA * gg.x + ee.x, 0.0f);
                oA.y = fmaxf((a4[1] - muA) * rsA * gg.y + ee.y, 0.0f);
                oB.x = fmaxf((a4[2] - muB) * rsB * gg.x + ee.x, 0.0f);
                oB.y = fmaxf((a4[3] - muB) * rsB * gg.y + ee.y, 0.0f);
                *(float2*)(outA + col) = oA;
                *(float2*)(outB + col) = oB;
            }
    }
}

// ---------------------------------------------------------------------------
extern "C" void kernel_launch(void* const* d_in, const int* in_sizes, int n_in,
                              void* d_out, int out_size)
{
    const float* x1    = (const float*)d_in[0];
    const float* x2    = (const float*)d_in[1];
    const float* S1    = (const float*)d_in[2];
    const float* S2    = (const float*)d_in[3];
    const float* W     = (const float*)d_in[4];
    const float* b     = (const float*)d_in[5];
    const float* gamma = (const float*)d_in[6];
    const float* beta  = (const float*)d_in[7];
    float* out = (float*)d_out;

    cudaFuncSetAttribute(k_main, cudaFuncAttributeMaxDynamicSharedMemorySize,
                         DSM_BYTES);

    k_extract<<<2 * DIM, 256>>>(S1, S2);
    k_build<<<1, 1024>>>();
    k_wprep<<<1024, 256>>>(W);
    k_main<<<BATCH / TB, NTHR, DSM_BYTES>>>(x1, x2, b, gamma, beta, out);
}

// round 17
// speedup vs baseline: 1.0550x; 1.0550x over previous
#include <cuda_runtime.h>
#include <cuda_bf16.h>
#include <cstdint>
#include <math.h>

// Problem constants
#define BATCH   8192
#define DIM     1024
#define SKETCH  8192
#define OUT     512
#define LN_EPS  1e-5f

#define MCAP    1024      // |J| <= 1024 (hard bound)
#define TB      64        // batch rows per CTA
#define NTHR    1024      // 32 warps
#define KCH     128       // K per chunk (64 kpairs)
#define APKS    72        // Apk row stride in words (bank-bijective)
#define WBS     72        // WB staging stride in words
#define NPIECE  256       // output cols per staged piece (2 pieces)

// -------- dynamic smem layout (bytes) --------------------------------------
#define OFF_AH   0                       // Apk_hi [64 kp][72 w] = 18432
#define OFF_AL   18432                   // Apk_lo             = 18432
#define OFF_WH   36864                   // WB_hi [256 n][72 w] = 73728
#define OFF_WL   110592                  // WB_lo              = 73728
#define OFF_BIAS 184320                  // 512 f
#define OFF_PS   186368                  // [64][8] f
#define OFF_PQ   188416                  // [64][8] f
#define OFF_MU   190464                  // 64 f
#define OFF_RS   190720                  // 64 f
#define DSM_BYTES 190976

// ---------------- device globals (scratch; no cudaMalloc allowed) ----------
__device__ unsigned int g_idx1[DIM];
__device__ unsigned int g_idx2[DIM];
__device__ int          g_m;
__device__ int          g_fallback;
__device__ int          g_colJ[MCAP];
__device__ int          g_cp1[MCAP + 1];
__device__ int          g_cp2[MCAP + 1];
__device__ unsigned int g_ent1[MCAP];
__device__ unsigned int g_ent2[MCAP];
__device__ ulonglong2   g_rec[MCAP];
// pre-split packed W: [n=512][kpair=512] bf16x2 words (1MB each)
__device__ unsigned int g_WBh[512 * 512];
__device__ unsigned int g_WBl[512 * 512];

// -------- helpers ----------------------------------------------------------
__device__ __forceinline__ float sgnapply(float x, unsigned e) {
    return __int_as_float(__float_as_int(x) ^ (int)((e & 1024u) << 21));
}
// bf16 3-split store: hi + lo halfwords into packed [kpair][row] tiles
__device__ __forceinline__ void put_split(char* bh, char* bl, int cl, int r, float v) {
    __nv_bfloat16 h = __float2bfloat16(v);
    __nv_bfloat16 l = __float2bfloat16(v - __bfloat162float(h));
    unsigned off = (unsigned)(((cl >> 1) * APKS + r) * 4 + (cl & 1) * 2);
    *(__nv_bfloat16*)(bh + off) = h;
    *(__nv_bfloat16*)(bl + off) = l;
}
// m16n8k16 bf16 MMA, fp32 accumulate in place
__device__ __forceinline__ void mma_bf16(float* d, const unsigned* a, const unsigned* b) {
    asm volatile(
        "mma.sync.aligned.m16n8k16.row.col.f32.bf16.bf16.f32 "
        "{%0,%1,%2,%3}, {%4,%5,%6,%7}, {%8,%9}, {%0,%1,%2,%3};"
        : "+f"(d[0]), "+f"(d[1]), "+f"(d[2]), "+f"(d[3])
        : "r"(a[0]), "r"(a[1]), "r"(a[2]), "r"(a[3]), "r"(b[0]), "r"(b[1]));
}

// -------- warp-shuffle block scan (1024 threads) ---------------------------
__device__ __forceinline__ int block_scan_incl(int val, int t, int* ws) {
    const unsigned full = 0xFFFFFFFFu;
    int lane = t & 31;
#pragma unroll
    for (int o = 1; o < 32; o <<= 1) {
        int n = __shfl_up_sync(full, val, o);
        if (lane >= o) val += n;
    }
    if (lane == 31) ws[t >> 5] = val;
    __syncthreads();
    if (t < 32) {
        int v = ws[t];
#pragma unroll
        for (int o = 1; o < 32; o <<= 1) {
            int n = __shfl_up_sync(full, v, o);
            if (t >= o) v += n;
        }
        ws[t] = v;
    }
    __syncthreads();
    if (t >= 32) val += ws[(t >> 5) - 1];
    return val;
}

// ---------------------------------------------------------------------------
// Kernel A: find the single nonzero per row of S1/S2.
// ---------------------------------------------------------------------------
__global__ void k_extract(const float* __restrict__ S1,
                          const float* __restrict__ S2)
{
    int row = blockIdx.x;
    const float* S;
    unsigned int* outp;
    if (row < DIM) { S = S1; outp = g_idx1; }
    else           { S = S2; outp = g_idx2; row -= DIM; }

    const float4* p = (const float4*)(S + (size_t)row * SKETCH);
    int t = threadIdx.x;
#pragma unroll
    for (int k = 0; k < SKETCH / 4 / 256; k++) {
        int v4 = t + k * 256;
        float4 v = p[v4];
        int base = v4 * 4;
        if (v.x != 0.0f) outp[row] = (unsigned)(base + 0) | (v.x < 0.0f ? 0x80000000u : 0u);
        if (v.y != 0.0f) outp[row] = (unsigned)(base + 1) | (v.y < 0.0f ? 0x80000000u : 0u);
        if (v.z != 0.0f) outp[row] = (unsigned)(base + 2) | (v.z < 0.0f ? 0x80000000u : 0u);
        if (v.w != 0.0f) outp[row] = (unsigned)(base + 3) | (v.w < 0.0f ? 0x80000000u : 0u);
    }
}

// ---------------------------------------------------------------------------
// Kernel B: build compact structure + CSR + packed records. 1 CTA, 1024 thr.
// ---------------------------------------------------------------------------
__global__ void k_build()
{
    __shared__ int cnt[SKETCH];
    __shared__ int colcnt[MCAP];
    __shared__ int ws[32];
    __shared__ int sh_total;

    int t = threadIdx.x;
    for (int j = t; j < SKETCH; j += 1024) cnt[j] = 0;
    if (t == 0) g_fallback = 0;
    __syncthreads();

    unsigned u1 = g_idx1[t];
    unsigned u2 = g_idx2[t];
    atomicAdd(&cnt[u1 & (SKETCH - 1)], 1);
    atomicAdd(&cnt[u2 & (SKETCH - 1)], 1 << 16);
    __syncthreads();

    int q = 0;
    int qual[8];
#pragma unroll
    for (int u = 0; u < 8; u++) {
        int j = t * 8 + u;
        int c = cnt[j];
        qual[u] = ((c & 0xFFFF) > 0 && (c >> 16) > 0) ? 1 : 0;
        q += qual[u];
    }
    int incl = block_scan_incl(q, t, ws);
    int excl = incl - q;
    if (t == 1023) sh_total = incl;
    __syncthreads();
    int total = sh_total;

#pragma unroll
    for (int u = 0; u < 8; u++) {
        int j = t * 8 + u;
        if (qual[u]) { g_colJ[excl] = j; cnt[j] = excl; excl++; }
        else         { cnt[j] = -1; }
    }
    if (t == 0) g_m = total;
    __syncthreads();

    int c1 = cnt[u1 & (SKETCH - 1)];
    int c2 = cnt[u2 & (SKETCH - 1)];
#pragma unroll
    for (int s = 0; s < 2; s++) {
        int cc = s ? c2 : c1;
        unsigned uu = s ? u2 : u1;
        int* cp = s ? g_cp2 : g_cp1;
        unsigned int* ent = s ? g_ent2 : g_ent1;

        colcnt[t] = 0;
        __syncthreads();
        if (cc >= 0) atomicAdd(&colcnt[cc], 1);
        __syncthreads();

        int myc = colcnt[t];
        int inc2 = block_scan_incl(myc, t, ws);
        int ex = inc2 - myc;
        cp[t] = ex;
        if (t == 1023) cp[1024] = inc2;
        __syncthreads();
        colcnt[t] = ex;
        __syncthreads();
        if (cc >= 0) {
            int slot = atomicAdd(&colcnt[cc], 1);
            ent[slot] = (((uu >> 31) & 1u) << 15) | (unsigned)t;
        }
        __syncthreads();
    }

    if (t < total) {
        unsigned long long w[2];
#pragma unroll
        for (int s = 0; s < 2; s++) {
            const int* cp = s ? g_cp2 : g_cp1;
            const unsigned int* ent = s ? g_ent2 : g_ent1;
            int e0 = cp[t], e1 = cp[t + 1];
            int cnte = e1 - e0;
            if (cnte > 4) { atomicOr(&g_fallback, 1); cnte = 4; }
            unsigned long long u = 0;
            for (int k = 0; k < cnte; k++) {
                unsigned v = ent[e0 + k];
                u |= (unsigned long long)((v & 1023u) | (((v >> 15) & 1u) << 10)) << (11 * k);
            }
            u |= (unsigned long long)cnte << 60;
            w[s] = u;
        }
        ulonglong2 r;
        r.x = w[0];
        r.y = w[1];
        g_rec[t] = r;
    }
}

// ---------------------------------------------------------------------------
// Kernel Bw: pre-split W into packed bf16x2 hi/lo, layout [n][kpair].
// ---------------------------------------------------------------------------
__global__ void k_wprep(const float* __restrict__ W)
{
    int m = g_m;
    int idx = blockIdx.x * 256 + threadIdx.x;   // 512 n x 512 kp
    int kp = idx & 511;
    int n  = idx >> 9;
    int c0 = 2 * kp, c1 = 2 * kp + 1;
    float v0 = (c0 < m) ? __ldg(&W[(size_t)g_colJ[c0] * OUT + n]) : 0.0f;
    float v1 = (c1 < m) ? __ldg(&W[(size_t)g_colJ[c1] * OUT + n]) : 0.0f;
    __nv_bfloat16 h0 = __float2bfloat16(v0);
    __nv_bfloat16 l0 = __float2bfloat16(v0 - __bfloat162float(h0));
    __nv_bfloat16 h1 = __float2bfloat16(v1);
    __nv_bfloat16 l1 = __float2bfloat16(v1 - __bfloat162float(h1));
    unsigned wh = (unsigned)__bfloat16_as_ushort(h0) |
                  ((unsigned)__bfloat16_as_ushort(h1) << 16);
    unsigned wl = (unsigned)__bfloat16_as_ushort(l0) |
                  ((unsigned)__bfloat16_as_ushort(l1) << 16);
    g_WBh[n * 512 + kp] = wh;
    g_WBl[n * 512 + kp] = wl;
}

// stage one 256-col WB piece into smem (conflict-free STS, coalesced LDG)
#define STAGE_PIECE(piece_)                                                    \
    for (int i = tid; i < NPIECE * 64; i += NTHR) {                            \
        int n  = i >> 6;                                                       \
        int kp = i & 63;                                                       \
        size_t src = (size_t)((piece_) * NPIECE + n) * 512 + ck0 / 2 + kp;     \
        WHs[n * WBS + kp] = g_WBh[src];                                        \
        WLs[n * WBS + kp] = g_WBl[src];                                        \
    }

// ---------------------------------------------------------------------------
// Main fused kernel. TB=64 rows/CTA, 1024 threads (32 warps), 128 CTAs.
//  Per chunk, 3 full-CTA barriers total:
//   phase1 { stage WB piece0 + zero A pad + gather } -> bar
//   GEMM(piece0) -> bar -> stage piece1 -> bar -> GEMM(piece1)
//  GEMM: mma.sync bf16 m16n8k16 3-split (R15-proven layout, stride-72
//  bank-bijective fragment loads). Epilogue: +bias, LN, ReLU.
// ---------------------------------------------------------------------------
__global__ void __launch_bounds__(NTHR, 1)
k_main(const float* __restrict__ x1, const float* __restrict__ x2,
       const float* __restrict__ bias, const float* __restrict__ gamma,
       const float* __restrict__ beta, float* __restrict__ out)
{
    extern __shared__ __align__(16) char dsm[];
    const unsigned* AHw = (const unsigned*)(dsm + OFF_AH);
    const unsigned* ALw = (const unsigned*)(dsm + OFF_AL);
    unsigned* WHs = (unsigned*)(dsm + OFF_WH);
    unsigned* WLs = (unsigned*)(dsm + OFF_WL);

    int tid  = threadIdx.x;
    int lane = tid & 31;
    int wrp  = tid >> 5;
    int g    = lane >> 2;         // 0..7
    int t4   = lane & 3;          // 0..3
    int mt   = wrp >> 3;          // 0..3  -> rows [mt*16, +16)
    int ng   = wrp & 7;           // 0..7  -> cols [ng*32, +32) within piece
    int b0   = blockIdx.x * TB;

    int m  = g_m;
    int fb = g_fallback;
    int nch = (m + KCH - 1) / KCH;

    for (int i = tid; i < OUT; i += NTHR)
        *(float*)(dsm + OFF_BIAS + i * 4) = __ldg(&bias[i]);

    // accumulators: acc[piece][n8][frag]
    float acc[2][4][4];
#pragma unroll
    for (int a = 0; a < 2; a++)
#pragma unroll
        for (int b = 0; b < 4; b++)
#pragma unroll
            for (int c = 0; c < 4; c++) acc[a][b][c] = 0.0f;

    for (int ch = 0; ch < nch; ch++) {
        int ck0 = ch * KCH;
        int Cn  = min(KCH, m - ck0);
        int ClPad = (Cn + 1) & ~1;
        int kp0 = ClPad >> 1;              // first kp needing explicit zero

        // ---- phase 1: stage piece0 + zero A pad + gather (one barrier) ----
        STAGE_PIECE(0)
        {   // zero pad region kp in [kp0, 64), rows 0..63, hi+lo
            int nz = (64 - kp0) * 64;
            for (int i = tid; i < nz; i += NTHR) {
                int kp = kp0 + (i >> 6);
                int r  = i & 63;
                ((unsigned*)(dsm + OFF_AH))[kp * APKS + r] = 0u;
                ((unsigned*)(dsm + OFF_AL))[kp * APKS + r] = 0u;
            }
        }
        if (!fb) {
            int nw = ClPad * 32;
            for (int p = tid; p < nw; p += NTHR) {
                int cl = p >> 5;
                int r  = p & 31;
                int c  = ck0 + cl;
                if (c >= m) {
                    put_split(dsm + OFF_AH, dsm + OFF_AL, cl, r, 0.0f);
                    put_split(dsm + OFF_AH, dsm + OFF_AL, cl, r + 32, 0.0f);
                    continue;
                }
                ulonglong2 rec = __ldg(&g_rec[c]);
                size_t ro0 = (size_t)(b0 + r) * DIM;
                size_t ro1 = (size_t)(b0 + r + 32) * DIM;

                unsigned long long u = rec.x;
                int cnt1 = (int)(u >> 60);
                unsigned e = (unsigned)u & 0x7FFu;
                float s1a = sgnapply(__ldg(&x1[ro0 + (e & 1023u)]), e);
                float s1b = sgnapply(__ldg(&x1[ro1 + (e & 1023u)]), e);
#pragma unroll
                for (int k = 1; k < 4; k++) {
                    if (k < cnt1) {
                        e = (unsigned)(u >> (11 * k)) & 0x7FFu;
                        s1a += sgnapply(__ldg(&x1[ro0 + (e & 1023u)]), e);
                        s1b += sgnapply(__ldg(&x1[ro1 + (e & 1023u)]), e);
                    }
                }
                u = rec.y;
                int cnt2 = (int)(u >> 60);
                e = (unsigned)u & 0x7FFu;
                float s2a = sgnapply(__ldg(&x2[ro0 + (e & 1023u)]), e);
                float s2b = sgnapply(__ldg(&x2[ro1 + (e & 1023u)]), e);
#pragma unroll
                for (int k = 1; k < 4; k++) {
                    if (k < cnt2) {
                        e = (unsigned)(u >> (11 * k)) & 0x7FFu;
                        s2a += sgnapply(__ldg(&x2[ro0 + (e & 1023u)]), e);
                        s2b += sgnapply(__ldg(&x2[ro1 + (e & 1023u)]), e);
                    }
                }
                put_split(dsm + OFF_AH, dsm + OFF_AL, cl, r,      s1a * s2a);
                put_split(dsm + OFF_AH, dsm + OFF_AL, cl, r + 32, s1b * s2b);
            }
        } else {
            int nw = ClPad * TB;
            for (int p = tid; p < nw; p += NTHR) {
                int cl = p >> 6;
                int r  = p & 63;
                int c  = ck0 + cl;
                float v = 0.0f;
                if (c < m) {
                    size_t rowoff = (size_t)(b0 + r) * DIM;
                    float s1 = 0.0f;
                    int e0 = __ldg(&g_cp1[c]), e1 = __ldg(&g_cp1[c + 1]);
                    for (int e = e0; e < e1; e++) {
                        unsigned u = __ldg(&g_ent1[e]);
                        float x = __ldg(&x1[rowoff + (u & 1023u)]);
                        s1 += (u & 0x8000u) ? -x : x;
                    }
                    float s2 = 0.0f;
                    int f0 = __ldg(&g_cp2[c]), f1 = __ldg(&g_cp2[c + 1]);
                    for (int e = f0; e < f1; e++) {
                        unsigned u = __ldg(&g_ent2[e]);
                        float x = __ldg(&x2[rowoff + (u & 1023u)]);
                        s2 += (u & 0x8000u) ? -x : x;
                    }
                    v = s1 * s2;
                }
                put_split(dsm + OFF_AH, dsm + OFF_AL, cl, r, v);
            }
        }
        __syncthreads();

        // ---- 2 pieces of 256 cols ----
#pragma unroll
        for (int pc = 0; pc < 2; pc++) {
            if (pc > 0) {
                __syncthreads();           // GEMM(piece0) done reading WB
                STAGE_PIECE(1)
                __syncthreads();
            }
            int arow = mt * 16 + g;
#pragma unroll
            for (int ks = 0; ks < 8; ks++) {
                unsigned ah[4], al[4];
                int kpa = ks * 8 + t4;
                ah[0] = AHw[kpa * APKS + arow];
                ah[1] = AHw[kpa * APKS + arow + 8];
                ah[2] = AHw[(kpa + 4) * APKS + arow];
                ah[3] = AHw[(kpa + 4) * APKS + arow + 8];
                al[0] = ALw[kpa * APKS + arow];
                al[1] = ALw[kpa * APKS + arow + 8];
                al[2] = ALw[(kpa + 4) * APKS + arow];
                al[3] = ALw[(kpa + 4) * APKS + arow + 8];
#pragma unroll
                for (int n8 = 0; n8 < 4; n8++) {
                    int nrow = ng * 32 + n8 * 8 + g;
                    unsigned bh[2], bl[2];
                    bh[0] = WHs[nrow * WBS + kpa];
                    bh[1] = WHs[nrow * WBS + kpa + 4];
                    bl[0] = WLs[nrow * WBS + kpa];
                    bl[1] = WLs[nrow * WBS + kpa + 4];
                    mma_bf16(acc[pc][n8], ah, bh);
                    mma_bf16(acc[pc][n8], ah, bl);
                    mma_bf16(acc[pc][n8], al, bh);
                }
            }
        }
        __syncthreads();       // A/WB rewritten next chunk (or reused by LN)
    }

    // -------- epilogue: +bias, LN stats --------------------------------
    float* PS = (float*)(dsm + OFF_PS);
    float* PQ = (float*)(dsm + OFF_PQ);
    float sA = 0.0f, qA = 0.0f, sB = 0.0f, qB = 0.0f;
#pragma unroll
    for (int pc = 0; pc < 2; pc++)
#pragma unroll
        for (int n8 = 0; n8 < 4; n8++) {
            int col = pc * NPIECE + ng * 32 + n8 * 8 + 2 * t4;
            float2 bb = *(float2*)(dsm + OFF_BIAS + col * 4);
            float* a4 = acc[pc][n8];
            a4[0] += bb.x; a4[1] += bb.y;
            a4[2] += bb.x; a4[3] += bb.y;
            sA += a4[0] + a4[1]; qA += a4[0] * a4[0] + a4[1] * a4[1];
            sB += a4[2] + a4[3]; qB += a4[2] * a4[2] + a4[3] * a4[3];
        }
#pragma unroll
    for (int o = 1; o < 4; o <<= 1) {
        sA += __shfl_xor_sync(0xFFFFFFFFu, sA, o);
        qA += __shfl_xor_sync(0xFFFFFFFFu, qA, o);
        sB += __shfl_xor_sync(0xFFFFFFFFu, sB, o);
        qB += __shfl_xor_sync(0xFFFFFFFFu, qB, o);
    }
    if (t4 == 0) {
        int rA = mt * 16 + g, rB = rA + 8;
        PS[rA * 8 + ng] = sA; PQ[rA * 8 + ng] = qA;
        PS[rB * 8 + ng] = sB; PQ[rB * 8 + ng] = qB;
    }
    __syncthreads();
    if (tid < TB) {
        float s = 0.0f, q = 0.0f;
#pragma unroll
        for (int w = 0; w < 8; w++) { s += PS[tid * 8 + w]; q += PQ[tid * 8 + w]; }
        float mu  = s * (1.0f / OUT);
        float var = q * (1.0f / OUT) - mu * mu;
        *(float*)(dsm + OFF_MU + tid * 4) = mu;
        *(float*)(dsm + OFF_RS + tid * 4) = rsqrtf(var + LN_EPS);
    }
    __syncthreads();

    // -------- normalize + affine + ReLU + store ------------------------
    {
        int rA = mt * 16 + g, rB = rA + 8;
        float muA = *(float*)(dsm + OFF_MU + rA * 4);
        float rsA = *(float*)(dsm + OFF_RS + rA * 4);
        float muB = *(float*)(dsm + OFF_MU + rB * 4);
        float rsB = *(float*)(dsm + OFF_RS + rB * 4);
        float* outA = out + (size_t)(b0 + rA) * OUT;
        float* outB = out + (size_t)(b0 + rB) * OUT;
#pragma unroll
        for (int pc = 0; pc < 2; pc++)
#pragma unroll
            for (int n8 = 0; n8 < 4; n8++) {
                int col = pc * NPIECE + ng * 32 + n8 * 8 + 2 * t4;
                float2 gg = __ldg((const float2*)(gamma + col));
                float2 ee = __ldg((const float2*)(beta + col));
                const float* a4 = acc[pc][n8];
                float2 oA, oB;
                oA.x = fmaxf((a4[0] - muA) * rsA * gg.x + ee.x, 0.0f);
                oA.y = fmaxf((a4[1] - muA) * rsA * gg.y + ee.y, 0.0f);
                oB.x = fmaxf((a4[2] - muB) * rsB * gg.x + ee.x, 0.0f);
                oB.y = fmaxf((a4[3] - muB) * rsB * gg.y + ee.y, 0.0f);
                *(float2*)(outA + col) = oA;
                *(float2*)(outB + col) = oB;
            }
    }
}

// ---------------------------------------------------------------------------
extern "C" void kernel_launch(void* const* d_in, const int* in_sizes, int n_in,
                              void* d_out, int out_size)
{
    const float* x1    = (const float*)d_in[0];
    const float* x2    = (const float*)d_in[1];
    const float* S1    = (const float*)d_in[2];
    const float* S2    = (const float*)d_in[3];
    const float* W     = (const float*)d_in[4];
    const float* b     = (const float*)d_in[5];
    const float* gamma = (const float*)d_in[6];
    const float* beta  = (const float*)d_in[7];
    float* out = (float*)d_out;

    cudaFuncSetAttribute(k_main, cudaFuncAttributeMaxDynamicSharedMemorySize,
                         DSM_BYTES);

    k_extract<<<2 * DIM, 256>>>(S1, S2);
    k_build<<<1, 1024>>>();
    k_wprep<<<1024, 256>>>(W);
    k_main<<<BATCH / TB, NTHR, DSM_BYTES>>>(x1, x2, b, gamma, beta, out);
}